// round 3
// baseline (speedup 1.0000x reference)
#include <cuda_runtime.h>
#include <math.h>

// Problem constants
#define BATCH 8
#define FEAT  64
#define HW    262144             // 512*512
#define NSEG  33                 // ids 0..32 (0 = background)
#define NI    32

// Segment-max config
#define THREADS1 512             // 16 warps = 16 features per (b,fg) group
#define TILEPX   4096            // pixels per work unit
#define NTILE    (HW / TILEPX)   // 64
#define NBFG     (BATCH * 4)     // 32 (b, feature-group) groups
#define NU       (NBFG * NTILE)  // 2048 work units
#define NB       304             // 152 SMs * 2 CTAs

#define VEC_ELEMS (BATCH * NI * FEAT)   // 16384

// Per-(b,instance,feature) maxima as float bit patterns (nonneg -> int order ok).
// Statically zeroed; the fused tail re-zeroes after consuming, so every call
// sees identical initial state.
__device__ int g_scratch[VEC_ELEMS];
__device__ unsigned int g_count;   // zero-init; tail resets to 0

extern __shared__ char smem_raw[];

// ---------------------------------------------------------------------------
// Fused kernel: persistent segment-max + last-block relation MLP.
//
// Segmax: block = 512 threads (16 warps); warp w <-> feature f = fg*16 + w.
// Private per-thread accumulators in smem: s_acc[id*512 + tid] (bank = tid%32,
// always conflict-free). Mask ids double-buffered; next tile's mask prefetched
// into registers during processing -> ONE __syncthreads per 4096-px tile.
//
// MLP (algebraically collapsed — no nonlinearity between layers):
//   out[b,c,j,i] = sigmoid( v_i.(W1a W2) + v_j.(W1b W2) + (b1 W2 + b2) )
// executed by the last block to finish, after a device-wide fence.
// ---------------------------------------------------------------------------
__global__ __launch_bounds__(THREADS1, 2)
void fused_kernel(const float* __restrict__ enc,
                  const int*   __restrict__ masks,
                  const float* __restrict__ w1,
                  const float* __restrict__ b1,
                  const float* __restrict__ w2,
                  const float* __restrict__ b2,
                  float*       __restrict__ out_vec,
                  float*       __restrict__ out_conn) {
    float* s_acc = (float*)smem_raw;                        // 33*512 floats = 67584 B
    int*   s_ids = (int*)(smem_raw + NSEG * THREADS1 * 4);  // 2*4096 ints  = 32768 B

    const int tid  = threadIdx.x;
    const int lane = tid & 31;
    const int w    = tid >> 5;
    const int k    = blockIdx.x;

    const int s = (k * NU) / NB;
    const int e = ((k + 1) * NU) / NB;

    int cur = s >> 6;                       // bfg of first unit
    int b   = s >> 8;
    int f   = ((cur & 3) << 4) | w;

    // ---- prologue: zero accumulators, stage ids for unit s ----
    #pragma unroll
    for (int r = 0; r < NSEG; ++r) s_acc[(r << 9) + tid] = 0.0f;
    {
        const int4* mp = (const int4*)(masks + (size_t)(s >> 8) * HW + (s & 63) * TILEPX);
        const int4 a0 = mp[tid];
        const int4 a1 = mp[tid + THREADS1];
        int4* dst = (int4*)s_ids;
        dst[tid]            = make_int4(a0.x << 9, a0.y << 9, a0.z << 9, a0.w << 9);
        dst[tid + THREADS1] = make_int4(a1.x << 9, a1.y << 9, a1.z << 9, a1.w << 9);
    }
    __syncthreads();

    int p = 0;
    for (int u = s; u < e; ++u) {
        // prefetch next tile's mask into registers (overlaps with processing)
        int4 m0, m1;
        const bool pf = (u + 1) < e;
        if (pf) {
            const int un = u + 1;
            const int4* mp = (const int4*)(masks + (size_t)(un >> 8) * HW + (un & 63) * TILEPX);
            m0 = mp[tid];
            m1 = mp[tid + THREADS1];
        }

        // (b,fg) boundary: flush old accumulators (thread-private cols -> no sync)
        const int bfg = u >> 6;
        if (bfg != cur) {
            #pragma unroll
            for (int id = 1; id < NSEG; ++id) {
                float v = s_acc[(id << 9) + tid];
                #pragma unroll
                for (int off = 16; off; off >>= 1)
                    v = fmaxf(v, __shfl_xor_sync(0xffffffffu, v, off));
                if (lane == 0 && v > 0.0f)
                    atomicMax(&g_scratch[(b * NI + (id - 1)) * FEAT + f],
                              __float_as_int(v));
            }
            #pragma unroll
            for (int r = 0; r < NSEG; ++r) s_acc[(r << 9) + tid] = 0.0f;
            cur = bfg;
            b   = bfg >> 2;
            f   = ((bfg & 3) << 4) | w;
        }

        // process tile u (each warp covers all 4096 px for its feature)
        const float4* src4 = (const float4*)enc
                           + (size_t)(b * FEAT + f) * (HW / 4)
                           + (u & 63) * (TILEPX / 4);
        const int4* id4 = (const int4*)(s_ids + p * TILEPX);

        #pragma unroll 4
        for (int g = 0; g < TILEPX / 4 / 32; ++g) {   // 32 iterations
            const int idx = g * 32 + lane;
            const float4 v = src4[idx];
            const int4  o = id4[idx];
            float a;
            a = s_acc[o.x + tid]; if (v.x > a) s_acc[o.x + tid] = v.x;
            a = s_acc[o.y + tid]; if (v.y > a) s_acc[o.y + tid] = v.y;
            a = s_acc[o.z + tid]; if (v.z > a) s_acc[o.z + tid] = v.z;
            a = s_acc[o.w + tid]; if (v.w > a) s_acc[o.w + tid] = v.w;
        }

        // commit prefetched ids into the other buffer
        if (pf) {
            int4* dst = (int4*)(s_ids + (p ^ 1) * TILEPX);
            dst[tid]            = make_int4(m0.x << 9, m0.y << 9, m0.z << 9, m0.w << 9);
            dst[tid + THREADS1] = make_int4(m1.x << 9, m1.y << 9, m1.z << 9, m1.w << 9);
        }
        __syncthreads();
        p ^= 1;
    }

    // final flush
    #pragma unroll
    for (int id = 1; id < NSEG; ++id) {
        float v = s_acc[(id << 9) + tid];
        #pragma unroll
        for (int off = 16; off; off >>= 1)
            v = fmaxf(v, __shfl_xor_sync(0xffffffffu, v, off));
        if (lane == 0 && v > 0.0f)
            atomicMax(&g_scratch[(b * NI + (id - 1)) * FEAT + f],
                      __float_as_int(v));
    }

    // ---- last-block-out runs the collapsed MLP ----
    __threadfence();
    __shared__ unsigned int s_rank;
    if (tid == 0) s_rank = atomicAdd(&g_count, 1u);
    __syncthreads();
    if (s_rank != NB - 1) return;
    __threadfence();   // acquire: all blocks' atomicMax results now visible

    // reuse dynamic smem
    float* s_w1 = (float*)smem_raw;        // 4096
    float* s_w2 = s_w1 + 4096;             // 128
    float* s_b1 = s_w2 + 128;              // 32
    float* s_b2 = s_b1 + 32;               // 4
    float* s_m1 = s_b2 + 4;                // 256: (W1a W2)[k][c]
    float* s_m2 = s_m1 + 256;              // 256: (W1b W2)[k][c]
    float* s_c0 = s_m2 + 256;              // 4
    float* s_v  = s_c0 + 4;                // 2 * 32*65 (padded)
    float* s_P  = s_v + 2 * 2080;          // 2 * 128
    float* s_Q  = s_P + 256;               // 2 * 128

    // stage weights (coalesced float4)
    ((float4*)s_w1)[tid]       = ((const float4*)w1)[tid];
    ((float4*)s_w1)[tid + 512] = ((const float4*)w1)[tid + 512];
    if (tid < 32) ((float4*)s_w2)[tid] = ((const float4*)w2)[tid];
    if (tid < 8)  ((float4*)s_b1)[tid] = ((const float4*)b1)[tid];
    if (tid < 4)  s_b2[tid] = b2[tid];
    __syncthreads();

    // fold: m1[k][c] = sum_m w1[k][m] w2[m][c]; m2 likewise for w1[64+k]
    if (tid < 256) {
        const int kk = tid >> 2, c = tid & 3;
        float a1 = 0.0f, a2 = 0.0f;
        #pragma unroll 8
        for (int m = 0; m < 32; ++m) {
            const float w2v = s_w2[m * 4 + c];
            a1 += s_w1[kk * 32 + m] * w2v;
            a2 += s_w1[(64 + kk) * 32 + m] * w2v;
        }
        s_m1[tid] = a1;
        s_m2[tid] = a2;
    } else if (tid < 260) {
        const int c = tid - 256;
        float a = s_b2[c];
        #pragma unroll 8
        for (int m = 0; m < 32; ++m) a += s_b1[m] * s_w2[m * 4 + c];
        s_c0[c] = a;
    }
    __syncthreads();

    // two batches per round
    for (int bb = 0; bb < BATCH; bb += 2) {
        for (int t = tid; t < 2 * NI * FEAT; t += THREADS1) {
            const int bloc = t >> 11;
            const int loc  = t & 2047;
            const int gidx = (bb + bloc) * NI * FEAT + loc;
            const float vv = __int_as_float(g_scratch[gidx]);
            s_v[bloc * 2080 + (loc >> 6) * 65 + (loc & 63)] = vv;
            out_vec[gidx]   = vv;
            g_scratch[gidx] = 0;
        }
        __syncthreads();

        {   // P[i][c] = v_i . m1_c ; Q[j][c] = v_j . m2_c   (512 threads exactly)
            const int bloc = tid >> 8;
            const int t2   = tid & 255;
            const int isQ  = t2 >> 7;
            const int idx  = t2 & 127;
            const int r = idx >> 2, c = idx & 3;
            const float* vm = s_v + bloc * 2080 + r * 65;
            const float* mm = isQ ? s_m2 : s_m1;
            float a = 0.0f;
            #pragma unroll 8
            for (int kk = 0; kk < FEAT; ++kk) a += vm[kk] * mm[kk * 4 + c];
            if (isQ) s_Q[bloc * 128 + idx] = a;
            else     s_P[bloc * 128 + idx] = a;
        }
        __syncthreads();

        #pragma unroll
        for (int rr = 0; rr < 16; ++rr) {
            const int o     = rr * THREADS1 + tid;   // 0..8191
            const int bloc  = o >> 12;
            const int oo    = o & 4095;              // c*1024 + j*32 + i
            const int c  = oo >> 10;
            const int j  = (oo >> 5) & 31;
            const int i  = oo & 31;
            const float t = s_P[bloc * 128 + i * 4 + c]
                          + s_Q[bloc * 128 + j * 4 + c] + s_c0[c];
            out_conn[(size_t)(bb + bloc) * 4096 + oo] = 1.0f / (1.0f + __expf(-t));
        }
        __syncthreads();
    }

    if (tid == 0) g_count = 0;   // restore state for next identical call
}

// ---------------------------------------------------------------------------
// Launch
// ---------------------------------------------------------------------------
extern "C" void kernel_launch(void* const* d_in, const int* in_sizes, int n_in,
                              void* d_out, int out_size) {
    const float* enc   = (const float*)d_in[0];
    const int*   masks = (const int*)d_in[1];
    const float* w1    = (const float*)d_in[2];
    const float* b1    = (const float*)d_in[3];
    const float* w2    = (const float*)d_in[4];
    const float* b2    = (const float*)d_in[5];

    float* out_vec  = (float*)d_out;
    float* out_conn = out_vec + VEC_ELEMS;

    static bool attr_set = false;
    const int smem_bytes = NSEG * THREADS1 * 4 + 2 * TILEPX * 4;  // 100352
    if (!attr_set) {
        cudaFuncSetAttribute(fused_kernel,
                             cudaFuncAttributeMaxDynamicSharedMemorySize, smem_bytes);
        attr_set = true;
    }

    fused_kernel<<<NB, THREADS1, smem_bytes>>>(enc, masks, w1, b1, w2, b2,
                                               out_vec, out_conn);
}

// round 4
// speedup vs baseline: 1.0516x; 1.0516x over previous
#include <cuda_runtime.h>
#include <math.h>

// Problem constants
#define BATCH 8
#define FEAT  64
#define HW    262144             // 512*512
#define NSEG  33                 // ids 0..32 (0 = background)
#define NI    32

// Segment-max config
#define THREADS1 512             // 16 warps = 16 features per (b,fg) group
#define TILEPX   2048            // pixels per work unit
#define NTILE    (HW / TILEPX)   // 128
#define NBFG     (BATCH * 4)     // 32 (b, feature-group) groups
#define NU       (NBFG * NTILE)  // 4096 work units
#define NB       456             // 152 SMs * 3 CTAs

#define VEC_ELEMS (BATCH * NI * FEAT)   // 16384

// Per-(b,instance,feature) maxima as float bit patterns (nonneg -> int order ok).
// Statically zeroed; the fused tail re-zeroes after consuming, so every call
// sees identical initial state.
__device__ int g_scratch[VEC_ELEMS];
__device__ unsigned int g_count;   // zero-init; tail resets to 0

extern __shared__ char smem_raw[];

// ---------------------------------------------------------------------------
// Fused kernel: persistent segment-max + last-block relation MLP.
//
// Segmax: block = 512 threads (16 warps); warp w <-> feature f = fg*16 + w.
// Private per-thread accumulators in smem: s_acc[id*512 + tid] (bank = tid%32,
// always conflict-free). Update is UNconditional fmaxf (LDS->FMNMX->STS,
// no predicate latency in the chain). Next tile's mask ids are prefetched
// into registers during processing (single smem id buffer -> 3 CTAs/SM).
//
// MLP (algebraically collapsed — no nonlinearity between layers):
//   out[b,c,j,i] = sigmoid( v_i.(W1a W2) + v_j.(W1b W2) + (b1 W2 + b2) )
// executed by the last block to finish, after a device-wide fence.
// ---------------------------------------------------------------------------
__global__ __launch_bounds__(THREADS1, 3)
void fused_kernel(const float* __restrict__ enc,
                  const int*   __restrict__ masks,
                  const float* __restrict__ w1,
                  const float* __restrict__ b1,
                  const float* __restrict__ w2,
                  const float* __restrict__ b2,
                  float*       __restrict__ out_vec,
                  float*       __restrict__ out_conn) {
    float* s_acc = (float*)smem_raw;                        // 33*512 floats = 67584 B
    int*   s_ids = (int*)(smem_raw + NSEG * THREADS1 * 4);  // 2048 ints    =  8192 B

    const int tid  = threadIdx.x;
    const int lane = tid & 31;
    const int w    = tid >> 5;
    const int k    = blockIdx.x;

    const int s = (k * NU) / NB;
    const int e = ((k + 1) * NU) / NB;

    int cur = s >> 7;                       // bfg of first unit (128 tiles per bfg)
    int b   = cur >> 2;
    int f   = ((cur & 3) << 4) | w;

    // ---- prologue: zero accumulators, stage ids for unit s ----
    #pragma unroll
    for (int r = 0; r < NSEG; ++r) s_acc[(r << 9) + tid] = 0.0f;
    {
        const int4 a0 = ((const int4*)(masks + (size_t)b * HW + (s & 127) * TILEPX))[tid];
        ((int4*)s_ids)[tid] = make_int4(a0.x << 9, a0.y << 9, a0.z << 9, a0.w << 9);
    }
    __syncthreads();

    for (int u = s; u < e; ++u) {
        // prefetch next tile's mask into registers (overlaps with processing)
        int4 m0;
        const bool pf = (u + 1) < e;
        if (pf) {
            const int un = u + 1;
            m0 = ((const int4*)(masks + (size_t)(un >> 9) * HW + (un & 127) * TILEPX))[tid];
        }

        // (b,fg) boundary: flush old accumulators (thread-private cols -> no sync)
        const int bfg = u >> 7;
        if (bfg != cur) {
            #pragma unroll
            for (int id = 1; id < NSEG; ++id) {
                float v = s_acc[(id << 9) + tid];
                #pragma unroll
                for (int off = 16; off; off >>= 1)
                    v = fmaxf(v, __shfl_xor_sync(0xffffffffu, v, off));
                if (lane == 0 && v > 0.0f)
                    atomicMax(&g_scratch[(b * NI + (id - 1)) * FEAT + f],
                              __float_as_int(v));
            }
            #pragma unroll
            for (int r = 0; r < NSEG; ++r) s_acc[(r << 9) + tid] = 0.0f;
            cur = bfg;
            b   = bfg >> 2;
            f   = ((bfg & 3) << 4) | w;
        }

        // process tile u (each warp covers all 2048 px for its feature)
        const float4* src4 = (const float4*)enc
                           + (size_t)(b * FEAT + f) * (HW / 4)
                           + (u & 127) * (TILEPX / 4);
        const int4* id4 = (const int4*)s_ids;

        #pragma unroll 4
        for (int g = 0; g < TILEPX / 4 / 32; ++g) {   // 16 iterations
            const int idx = g * 32 + lane;
            const float4 v = src4[idx];
            const int4  o = id4[idx];
            // Unconditional max: LDS -> FMNMX(4cy) -> STS, no predicate wait.
            s_acc[o.x + tid] = fmaxf(s_acc[o.x + tid], v.x);
            s_acc[o.y + tid] = fmaxf(s_acc[o.y + tid], v.y);
            s_acc[o.z + tid] = fmaxf(s_acc[o.z + tid], v.z);
            s_acc[o.w + tid] = fmaxf(s_acc[o.w + tid], v.w);
        }

        __syncthreads();   // everyone done reading s_ids
        if (pf) {
            ((int4*)s_ids)[tid] = make_int4(m0.x << 9, m0.y << 9, m0.z << 9, m0.w << 9);
        }
        __syncthreads();   // s_ids ready for next unit
    }

    // final flush
    #pragma unroll
    for (int id = 1; id < NSEG; ++id) {
        float v = s_acc[(id << 9) + tid];
        #pragma unroll
        for (int off = 16; off; off >>= 1)
            v = fmaxf(v, __shfl_xor_sync(0xffffffffu, v, off));
        if (lane == 0 && v > 0.0f)
            atomicMax(&g_scratch[(b * NI + (id - 1)) * FEAT + f],
                      __float_as_int(v));
    }

    // ---- last-block-out runs the collapsed MLP ----
    __threadfence();
    __shared__ unsigned int s_rank;
    if (tid == 0) s_rank = atomicAdd(&g_count, 1u);
    __syncthreads();
    if (s_rank != NB - 1) return;
    __threadfence();   // acquire: all blocks' atomicMax results now visible

    // reuse dynamic smem (tail needs ~38 KB < 75776 B)
    float* s_w1 = (float*)smem_raw;        // 4096
    float* s_w2 = s_w1 + 4096;             // 128
    float* s_b1 = s_w2 + 128;              // 32
    float* s_b2 = s_b1 + 32;               // 4
    float* s_m1 = s_b2 + 4;                // 256: (W1a W2)[k][c]
    float* s_m2 = s_m1 + 256;              // 256: (W1b W2)[k][c]
    float* s_c0 = s_m2 + 256;              // 4
    float* s_v  = s_c0 + 4;                // 2 * 32*65 (padded)
    float* s_P  = s_v + 2 * 2080;          // 2 * 128
    float* s_Q  = s_P + 256;               // 2 * 128

    // stage weights (coalesced float4)
    ((float4*)s_w1)[tid]       = ((const float4*)w1)[tid];
    ((float4*)s_w1)[tid + 512] = ((const float4*)w1)[tid + 512];
    if (tid < 32) ((float4*)s_w2)[tid] = ((const float4*)w2)[tid];
    if (tid < 8)  ((float4*)s_b1)[tid] = ((const float4*)b1)[tid];
    if (tid < 4)  s_b2[tid] = b2[tid];
    __syncthreads();

    // fold: m1[k][c] = sum_m w1[k][m] w2[m][c]; m2 likewise for w1[64+k]
    if (tid < 256) {
        const int kk = tid >> 2, c = tid & 3;
        float a1 = 0.0f, a2 = 0.0f;
        #pragma unroll 8
        for (int m = 0; m < 32; ++m) {
            const float w2v = s_w2[m * 4 + c];
            a1 += s_w1[kk * 32 + m] * w2v;
            a2 += s_w1[(64 + kk) * 32 + m] * w2v;
        }
        s_m1[tid] = a1;
        s_m2[tid] = a2;
    } else if (tid < 260) {
        const int c = tid - 256;
        float a = s_b2[c];
        #pragma unroll 8
        for (int m = 0; m < 32; ++m) a += s_b1[m] * s_w2[m * 4 + c];
        s_c0[c] = a;
    }
    __syncthreads();

    // two batches per round
    for (int bb = 0; bb < BATCH; bb += 2) {
        for (int t = tid; t < 2 * NI * FEAT; t += THREADS1) {
            const int bloc = t >> 11;
            const int loc  = t & 2047;
            const int gidx = (bb + bloc) * NI * FEAT + loc;
            const float vv = __int_as_float(g_scratch[gidx]);
            s_v[bloc * 2080 + (loc >> 6) * 65 + (loc & 63)] = vv;
            out_vec[gidx]   = vv;
            g_scratch[gidx] = 0;
        }
        __syncthreads();

        {   // P[i][c] = v_i . m1_c ; Q[j][c] = v_j . m2_c   (512 threads exactly)
            const int bloc = tid >> 8;
            const int t2   = tid & 255;
            const int isQ  = t2 >> 7;
            const int idx  = t2 & 127;
            const int r = idx >> 2, c = idx & 3;
            const float* vm = s_v + bloc * 2080 + r * 65;
            const float* mm = isQ ? s_m2 : s_m1;
            float a = 0.0f;
            #pragma unroll 8
            for (int kk = 0; kk < FEAT; ++kk) a += vm[kk] * mm[kk * 4 + c];
            if (isQ) s_Q[bloc * 128 + idx] = a;
            else     s_P[bloc * 128 + idx] = a;
        }
        __syncthreads();

        #pragma unroll
        for (int rr = 0; rr < 16; ++rr) {
            const int o     = rr * THREADS1 + tid;   // 0..8191
            const int bloc  = o >> 12;
            const int oo    = o & 4095;              // c*1024 + j*32 + i
            const int c  = oo >> 10;
            const int j  = (oo >> 5) & 31;
            const int i  = oo & 31;
            const float t = s_P[bloc * 128 + i * 4 + c]
                          + s_Q[bloc * 128 + j * 4 + c] + s_c0[c];
            out_conn[(size_t)(bb + bloc) * 4096 + oo] = 1.0f / (1.0f + __expf(-t));
        }
        __syncthreads();
    }

    if (tid == 0) g_count = 0;   // restore state for next identical call
}

// ---------------------------------------------------------------------------
// Launch
// ---------------------------------------------------------------------------
extern "C" void kernel_launch(void* const* d_in, const int* in_sizes, int n_in,
                              void* d_out, int out_size) {
    const float* enc   = (const float*)d_in[0];
    const int*   masks = (const int*)d_in[1];
    const float* w1    = (const float*)d_in[2];
    const float* b1    = (const float*)d_in[3];
    const float* w2    = (const float*)d_in[4];
    const float* b2    = (const float*)d_in[5];

    float* out_vec  = (float*)d_out;
    float* out_conn = out_vec + VEC_ELEMS;

    static bool attr_set = false;
    const int smem_bytes = NSEG * THREADS1 * 4 + TILEPX * 4;  // 75776
    if (!attr_set) {
        cudaFuncSetAttribute(fused_kernel,
                             cudaFuncAttributeMaxDynamicSharedMemorySize, smem_bytes);
        attr_set = true;
    }

    fused_kernel<<<NB, THREADS1, smem_bytes>>>(enc, masks, w1, b1, w2, b2,
                                               out_vec, out_conn);
}

// round 5
// speedup vs baseline: 1.0735x; 1.0208x over previous
#include <cuda_runtime.h>
#include <math.h>

// Problem constants
#define BATCH 8
#define FEAT  64
#define HW    262144             // 512*512
#define NSEG  33                 // ids 0..32 (0 = background)
#define NI    32

// Segment-max config
#define THREADS1 512             // 16 warps = 16 features per (b,fg) group
#define TILEPX   4096            // pixels per work unit
#define NTILE    (HW / TILEPX)   // 64
#define NBFG     (BATCH * 4)     // 32 (b, feature-group) groups
#define NU       (NBFG * NTILE)  // 2048 work units
#define NB       304             // 152 SMs * 2 CTAs

#define VEC_ELEMS (BATCH * NI * FEAT)   // 16384

// Per-(b,instance,feature) maxima as float bit patterns (nonneg -> int order ok).
__device__ int g_scratch[VEC_ELEMS];
__device__ unsigned int g_count;   // zero-init; tail resets to 0

extern __shared__ char smem_raw[];

// ---------------------------------------------------------------------------
// Fused kernel: persistent segment-max + last-block relation MLP.
//
// Segmax: 512 threads (16 warps); warp w <-> feature f = fg*16 + w.
// Private per-thread accumulators: s_acc[id*512 + tid] (bank = tid%32,
// conflict-free). enc values are loaded in register-double-buffered groups
// of 4 float4s (MLP ~4-8 per warp) so DRAM latency is covered; the fmax
// chains for group g overlap the in-flight loads of group g+1.
//
// MLP (collapsed — no nonlinearity between layers):
//   out[b,c,j,i] = sigmoid( v_i.(W1a W2) + v_j.(W1b W2) + (b1 W2 + b2) )
// run by the last block after a device-wide fence.
// ---------------------------------------------------------------------------
__global__ __launch_bounds__(THREADS1, 2)
void fused_kernel(const float* __restrict__ enc,
                  const int*   __restrict__ masks,
                  const float* __restrict__ w1,
                  const float* __restrict__ b1,
                  const float* __restrict__ w2,
                  const float* __restrict__ b2,
                  float*       __restrict__ out_vec,
                  float*       __restrict__ out_conn) {
    float* s_acc = (float*)smem_raw;                        // 33*512 floats = 67584 B
    int*   s_ids = (int*)(smem_raw + NSEG * THREADS1 * 4);  // 4096 ints    = 16384 B

    const int tid  = threadIdx.x;
    const int lane = tid & 31;
    const int w    = tid >> 5;
    const int k    = blockIdx.x;

    const int s = (k * NU) / NB;
    const int e = ((k + 1) * NU) / NB;

    int cur = s >> 6;                       // bfg of first unit (64 tiles per bfg)
    int b   = cur >> 2;
    int f   = ((cur & 3) << 4) | w;

    // ---- prologue: zero accumulators, stage ids for unit s ----
    #pragma unroll
    for (int r = 0; r < NSEG; ++r) s_acc[(r << 9) + tid] = 0.0f;
    {
        const int4* mp = (const int4*)(masks + (size_t)b * HW + (s & 63) * TILEPX);
        const int4 a0 = mp[tid];
        const int4 a1 = mp[tid + THREADS1];
        ((int4*)s_ids)[tid]            = make_int4(a0.x << 9, a0.y << 9, a0.z << 9, a0.w << 9);
        ((int4*)s_ids)[tid + THREADS1] = make_int4(a1.x << 9, a1.y << 9, a1.z << 9, a1.w << 9);
    }
    __syncthreads();

    for (int u = s; u < e; ++u) {
        // prefetch next tile's mask ids into registers (overlaps processing)
        int4 m0, m1;
        const bool pf = (u + 1) < e;
        if (pf) {
            const int un = u + 1;
            const int4* mp = (const int4*)(masks + (size_t)(un >> 8) * HW + (un & 63) * TILEPX);
            m0 = mp[tid];
            m1 = mp[tid + THREADS1];
        }

        // (b,fg) boundary: flush old accumulators (thread-private -> no sync)
        const int bfg = u >> 6;
        if (bfg != cur) {
            #pragma unroll
            for (int id = 1; id < NSEG; ++id) {
                float v = s_acc[(id << 9) + tid];
                #pragma unroll
                for (int off = 16; off; off >>= 1)
                    v = fmaxf(v, __shfl_xor_sync(0xffffffffu, v, off));
                if (lane == 0 && v > 0.0f)
                    atomicMax(&g_scratch[(b * NI + (id - 1)) * FEAT + f],
                              __float_as_int(v));
            }
            #pragma unroll
            for (int r = 0; r < NSEG; ++r) s_acc[(r << 9) + tid] = 0.0f;
            cur = bfg;
            b   = bfg >> 2;
            f   = ((bfg & 3) << 4) | w;
        }

        // process tile u: each warp covers all 4096 px for its feature.
        // 32 float4-iterations per thread, in 8 register-double-buffered
        // groups of 4 (16 outstanding loads' worth of latency hiding).
        const float4* src4 = (const float4*)enc
                           + (size_t)(b * FEAT + f) * (HW / 4)
                           + (u & 63) * (TILEPX / 4);
        const int4* id4 = (const int4*)s_ids;

        float4 vb[4];
        #pragma unroll
        for (int t = 0; t < 4; ++t) vb[t] = src4[t * 32 + lane];

        #pragma unroll
        for (int gb = 0; gb < 8; ++gb) {
            float4 vn[4];
            if (gb < 7) {
                #pragma unroll
                for (int t = 0; t < 4; ++t)
                    vn[t] = src4[(gb + 1) * 128 + t * 32 + lane];
            }
            #pragma unroll
            for (int t = 0; t < 4; ++t) {
                const int4 o = id4[gb * 128 + t * 32 + lane];
                const float4 v = vb[t];
                s_acc[o.x + tid] = fmaxf(s_acc[o.x + tid], v.x);
                s_acc[o.y + tid] = fmaxf(s_acc[o.y + tid], v.y);
                s_acc[o.z + tid] = fmaxf(s_acc[o.z + tid], v.z);
                s_acc[o.w + tid] = fmaxf(s_acc[o.w + tid], v.w);
            }
            #pragma unroll
            for (int t = 0; t < 4; ++t) vb[t] = vn[t];
        }

        __syncthreads();   // everyone done reading s_ids
        if (pf) {
            ((int4*)s_ids)[tid]            = make_int4(m0.x << 9, m0.y << 9, m0.z << 9, m0.w << 9);
            ((int4*)s_ids)[tid + THREADS1] = make_int4(m1.x << 9, m1.y << 9, m1.z << 9, m1.w << 9);
        }
        __syncthreads();   // s_ids ready for next unit
    }

    // final flush
    #pragma unroll
    for (int id = 1; id < NSEG; ++id) {
        float v = s_acc[(id << 9) + tid];
        #pragma unroll
        for (int off = 16; off; off >>= 1)
            v = fmaxf(v, __shfl_xor_sync(0xffffffffu, v, off));
        if (lane == 0 && v > 0.0f)
            atomicMax(&g_scratch[(b * NI + (id - 1)) * FEAT + f],
                      __float_as_int(v));
    }

    // ---- last-block-out runs the collapsed MLP ----
    __threadfence();
    __shared__ unsigned int s_rank;
    if (tid == 0) s_rank = atomicAdd(&g_count, 1u);
    __syncthreads();
    if (s_rank != NB - 1) return;
    __threadfence();   // acquire: all blocks' atomicMax results now visible

    // reuse dynamic smem (tail needs ~38 KB < 83968 B)
    float* s_w1 = (float*)smem_raw;        // 4096
    float* s_w2 = s_w1 + 4096;             // 128
    float* s_b1 = s_w2 + 128;              // 32
    float* s_b2 = s_b1 + 32;               // 4
    float* s_m1 = s_b2 + 4;                // 256: (W1a W2)[k][c]
    float* s_m2 = s_m1 + 256;              // 256: (W1b W2)[k][c]
    float* s_c0 = s_m2 + 256;              // 4
    float* s_v  = s_c0 + 4;                // 2 * 32*65 (padded)
    float* s_P  = s_v + 2 * 2080;          // 2 * 128
    float* s_Q  = s_P + 256;               // 2 * 128

    // stage weights (coalesced float4)
    ((float4*)s_w1)[tid]       = ((const float4*)w1)[tid];
    ((float4*)s_w1)[tid + 512] = ((const float4*)w1)[tid + 512];
    if (tid < 32) ((float4*)s_w2)[tid] = ((const float4*)w2)[tid];
    if (tid < 8)  ((float4*)s_b1)[tid] = ((const float4*)b1)[tid];
    if (tid < 4)  s_b2[tid] = b2[tid];
    __syncthreads();

    // fold: m1[k][c] = sum_m w1[k][m] w2[m][c]; m2 likewise for w1[64+k]
    if (tid < 256) {
        const int kk = tid >> 2, c = tid & 3;
        float a1 = 0.0f, a2 = 0.0f;
        #pragma unroll 8
        for (int m = 0; m < 32; ++m) {
            const float w2v = s_w2[m * 4 + c];
            a1 += s_w1[kk * 32 + m] * w2v;
            a2 += s_w1[(64 + kk) * 32 + m] * w2v;
        }
        s_m1[tid] = a1;
        s_m2[tid] = a2;
    } else if (tid < 260) {
        const int c = tid - 256;
        float a = s_b2[c];
        #pragma unroll 8
        for (int m = 0; m < 32; ++m) a += s_b1[m] * s_w2[m * 4 + c];
        s_c0[c] = a;
    }
    __syncthreads();

    // two batches per round
    for (int bb = 0; bb < BATCH; bb += 2) {
        for (int t = tid; t < 2 * NI * FEAT; t += THREADS1) {
            const int bloc = t >> 11;
            const int loc  = t & 2047;
            const int gidx = (bb + bloc) * NI * FEAT + loc;
            const float vv = __int_as_float(g_scratch[gidx]);
            s_v[bloc * 2080 + (loc >> 6) * 65 + (loc & 63)] = vv;
            out_vec[gidx]   = vv;
            g_scratch[gidx] = 0;
        }
        __syncthreads();

        {   // P[i][c] = v_i . m1_c ; Q[j][c] = v_j . m2_c   (512 threads exactly)
            const int bloc = tid >> 8;
            const int t2   = tid & 255;
            const int isQ  = t2 >> 7;
            const int idx  = t2 & 127;
            const int r = idx >> 2, c = idx & 3;
            const float* vm = s_v + bloc * 2080 + r * 65;
            const float* mm = isQ ? s_m2 : s_m1;
            float a = 0.0f;
            #pragma unroll 8
            for (int kk = 0; kk < FEAT; ++kk) a += vm[kk] * mm[kk * 4 + c];
            if (isQ) s_Q[bloc * 128 + idx] = a;
            else     s_P[bloc * 128 + idx] = a;
        }
        __syncthreads();

        #pragma unroll
        for (int rr = 0; rr < 16; ++rr) {
            const int o     = rr * THREADS1 + tid;   // 0..8191
            const int bloc  = o >> 12;
            const int oo    = o & 4095;              // c*1024 + j*32 + i
            const int c  = oo >> 10;
            const int j  = (oo >> 5) & 31;
            const int i  = oo & 31;
            const float t = s_P[bloc * 128 + i * 4 + c]
                          + s_Q[bloc * 128 + j * 4 + c] + s_c0[c];
            out_conn[(size_t)(bb + bloc) * 4096 + oo] = 1.0f / (1.0f + __expf(-t));
        }
        __syncthreads();
    }

    if (tid == 0) g_count = 0;   // restore state for next identical call
}

// ---------------------------------------------------------------------------
// Launch
// ---------------------------------------------------------------------------
extern "C" void kernel_launch(void* const* d_in, const int* in_sizes, int n_in,
                              void* d_out, int out_size) {
    const float* enc   = (const float*)d_in[0];
    const int*   masks = (const int*)d_in[1];
    const float* w1    = (const float*)d_in[2];
    const float* b1    = (const float*)d_in[3];
    const float* w2    = (const float*)d_in[4];
    const float* b2    = (const float*)d_in[5];

    float* out_vec  = (float*)d_out;
    float* out_conn = out_vec + VEC_ELEMS;

    static bool attr_set = false;
    const int smem_bytes = NSEG * THREADS1 * 4 + TILEPX * 4;  // 83968
    if (!attr_set) {
        cudaFuncSetAttribute(fused_kernel,
                             cudaFuncAttributeMaxDynamicSharedMemorySize, smem_bytes);
        attr_set = true;
    }

    fused_kernel<<<NB, THREADS1, smem_bytes>>>(enc, masks, w1, b1, w2, b2,
                                               out_vec, out_conn);
}